// round 13
// baseline (speedup 1.0000x reference)
#include <cuda_runtime.h>
#include <math.h>

#define NB    4      // batch
#define S     363    // sinogram length / recon grid
#define A     180    // angles
#define AH    90     // angles per half
#define W     256    // output size
#define RP    364    // table row entries, k in [0,363]

// tab2[pair][a][k] = (mid_b0, delta_b0, mid_b1, delta_b1) for batches
// (2*pair, 2*pair+1): delta = p[k]-p[k-1], mid = p[k-1]+0.5*delta, p[-1]=p[363]=0.
// Interp at q (=pos+1, round k of q-0.5): mid + t*delta, t = (q-0.5)-k.
__device__ float4 g_tab2[2][A * RP];
// angle-half partials, same layout as out: [half][n][yy][xx]
__device__ float g_part[2][NB * W * W];

// One block per (n, a) column. Spatial ramp-filter convolution, taps folded to
// immediates via full unroll; 4 accumulators break the serial FMA chain.
__global__ __launch_bounds__(384) void ramp_filter_kernel(const float* __restrict__ x) {
    const int na = blockIdx.x;
    const int n  = na / A;
    const int a  = na - n * A;

    __shared__ float xsp[S + 2 * 362];  // zeros | data | zeros
    __shared__ float ps[S + 2];         // p[-1..363], zero-padded ends

    const int t = threadIdx.x;
    if (t < 362) {
        xsp[t] = 0.0f;
        xsp[725 + t] = 0.0f;
    }
    if (t < 2) ps[t * 364] = 0.0f;      // ps[0]=p[-1]=0, ps[364]=p[363]=0
    // input layout: [n][1][s][a], a fastest
    for (int s = t; s < S; s += 384)
        xsp[362 + s] = x[(n * S + s) * A + a];
    __syncthreads();

    if (t < S) {
        const float* c = xsp + 362 + t;
        float ac0 = 0.5f * c[0], ac1 = 0.f, ac2 = 0.f, ac3 = 0.f;
        #pragma unroll
        for (int j = 0; j < 181; ++j) {
            const int d = 2 * j + 1;
            const float h = -2.0f / ((float)(M_PI * M_PI) * (float)d * (float)d);
            const float v = c[-d] + c[d];
            if ((j & 3) == 0)      ac0 = fmaf(v, h, ac0);
            else if ((j & 3) == 1) ac1 = fmaf(v, h, ac1);
            else if ((j & 3) == 2) ac2 = fmaf(v, h, ac2);
            else                   ac3 = fmaf(v, h, ac3);
        }
        ps[t + 1] = (ac0 + ac1) + (ac2 + ac3);
    }
    __syncthreads();

    // write this batch's (mid, delta) half of the packed pair table
    float2* gr = ((float2*)&g_tab2[n >> 1][(size_t)a * RP]) + (n & 1);
    if (t < RP) {                        // k = t in [0, 363]
        const float p0 = ps[t];          // p[k-1]
        const float p1 = ps[t + 1];      // p[k]
        const float d  = p1 - p0;
        gr[2 * t] = make_float2(fmaf(0.5f, d, p0), d);
    }
}

#define CH 3                     // angles per pipeline chunk (90/3 = 30, even)
#define NCHUNK (AH / CH)
#define MAGICF 12582912.0f       // 2^23 + 2^22
#define MAGICI 0x4B400000

// grid (8, 32, 2): block = 32(x) x 8(y) spatial tile x angle-half; warp =
// 8(x) x 4(y) patch for gather locality. ALL 4 batches per thread: one index
// feeds two LDG.128 (second at fixed byte offset). qp = xf*cos - yf*sin +
// 181.5; k = round(qp) via magic; value = mid + (qp-k)*delta.
__global__ __launch_bounds__(256) void backproject_kernel() {
    const int x0 = blockIdx.x * 32;
    const int y0 = blockIdx.y * 8;
    const int hf = blockIdx.z;
    const int abase = hf * AH;
    const int tid = threadIdx.x;
    const int w = tid >> 5, l = tid & 31;

    const int xx = x0 + ((w & 3) << 3) + (l & 7);
    const int yy = y0 + ((w >> 2) << 2) + (l >> 3);

    __shared__ float2 sc2[AH];   // (cos, sin) for angle abase+t

    if (tid < AH) {
        float sn, cs;
        sincosf((float)(abase + tid) * (float)(M_PI / 180.0), &sn, &cs);
        sc2[tid] = make_float2(cs, sn);
    }
    __syncthreads();

    const float xf = (float)(xx - 128);
    const float yf = (float)(yy - 128);
    const float4* __restrict__ tb0 = g_tab2[0] + (size_t)abase * RP;
    const float4* __restrict__ tb1 = g_tab2[1] + (size_t)abase * RP;

    float accm0 = 0.f, accm1 = 0.f, accm2 = 0.f, accm3 = 0.f;
    float accd0 = 0.f, accd1 = 0.f, accd2 = 0.f, accd3 = 0.f;

    float4 va0[CH], va1[CH], vb0[CH], vb1[CH];
    float  wa[CH], wb[CH];

    #define LOADC(c, v0, v1, ww)                                              \
        {                                                                     \
            const int a0 = (c) * CH;                                          \
            _Pragma("unroll")                                                 \
            for (int k = 0; k < CH; ++k) {                                    \
                const float2 cb = sc2[a0 + k];                                \
                const float qp = fmaf(xf, cb.x, fmaf(-yf, cb.y, 181.5f));     \
                const float f  = qp + MAGICF;                                 \
                const float il = f - MAGICF;             /* round(qp) */      \
                ww[k] = qp - il;                         /* in [-.5,.5] */    \
                const int i = (a0 + k) * RP + (__float_as_int(f) - MAGICI);   \
                v0[k] = __ldg(tb0 + i);                                       \
                v1[k] = __ldg(tb1 + i);                                       \
            }                                                                 \
        }

    #define ACCC(v0, v1, ww)                                                  \
        {                                                                     \
            _Pragma("unroll")                                                 \
            for (int k = 0; k < CH; ++k) {                                    \
                accm0 += v0[k].x;  accd0 = fmaf(ww[k], v0[k].y, accd0);       \
                accm1 += v0[k].z;  accd1 = fmaf(ww[k], v0[k].w, accd1);       \
                accm2 += v1[k].x;  accd2 = fmaf(ww[k], v1[k].y, accd2);       \
                accm3 += v1[k].z;  accd3 = fmaf(ww[k], v1[k].w, accd3);       \
            }                                                                 \
        }

    LOADC(0, va0, va1, wa)
    LOADC(1, vb0, vb1, wb)
    #pragma unroll 1
    for (int c = 0; c + 2 < NCHUNK; c += 2) {
        ACCC(va0, va1, wa)
        LOADC(c + 2, va0, va1, wa)
        ACCC(vb0, vb1, wb)
        LOADC(c + 3, vb0, vb1, wb)
    }
    ACCC(va0, va1, wa)
    ACCC(vb0, vb1, wb)

    #undef LOADC
    #undef ACCC

    float* o = g_part[hf] + (size_t)yy * W + xx;
    o[0 * W * W] = accm0 + accd0;
    o[1 * W * W] = accm1 + accd1;
    o[2 * W * W] = accm2 + accd2;
    o[3 * W * W] = accm3 + accd3;
}

// out = (part0 + part1) * pi/360, fully coalesced float4.
__global__ __launch_bounds__(256) void combine_kernel(float* __restrict__ out) {
    const int i = blockIdx.x * 256 + threadIdx.x;     // float4 index
    const float4 p0 = ((const float4*)g_part[0])[i];
    const float4 p1 = ((const float4*)g_part[1])[i];
    const float sc = (float)(M_PI / 360.0);
    float4 r;
    r.x = (p0.x + p1.x) * sc;
    r.y = (p0.y + p1.y) * sc;
    r.z = (p0.z + p1.z) * sc;
    r.w = (p0.w + p1.w) * sc;
    ((float4*)out)[i] = r;
}

extern "C" void kernel_launch(void* const* d_in, const int* in_sizes, int n_in,
                              void* d_out, int out_size) {
    const float* x = (const float*)d_in[0];
    float* out = (float*)d_out;

    ramp_filter_kernel<<<NB * A, 384>>>(x);
    backproject_kernel<<<dim3(8, 32, 2), 256>>>();
    combine_kernel<<<(NB * W * W / 4) / 256, 256>>>(out);
}

// round 15
// speedup vs baseline: 1.2070x; 1.2070x over previous
#include <cuda_runtime.h>
#include <math.h>

#define NB    4      // batch
#define S     363    // sinogram length / recon grid
#define A     180    // angles
#define AH    90     // angles per half
#define W     256    // output size
#define RP    364    // table row entries, k in [0,363]

// tab2[pair][a][k] = (mid_b0, delta_b0, mid_b1, delta_b1) for batches
// (2*pair, 2*pair+1): delta = p[k]-p[k-1], mid = p[k-1]+0.5*delta, p[-1]=p[363]=0.
// Interp at q (=pos+1, round k of q-0.5): mid + t*delta, t = (q-0.5)-k.
__device__ float4 g_tab2[2][A * RP];
// angle-half partials, same layout as out: [half][n][yy][xx]
__device__ float g_part[2][NB * W * W];

// One block per (n, a) column. Ramp-filter convolution with immediate weights;
// per-side bound guards (d<=t / d<=362-t) remove the zero-padding loads, which
// were exactly half of all LDS traffic.
__global__ __launch_bounds__(384) void ramp_filter_kernel(const float* __restrict__ x) {
    const int na = blockIdx.x;
    const int n  = na / A;
    const int a  = na - n * A;

    __shared__ float xs[S];
    __shared__ float ps[S + 2];         // p[-1..363], zero-padded ends

    const int t = threadIdx.x;
    if (t < 2) ps[t * 364] = 0.0f;      // ps[0]=p[-1]=0, ps[364]=p[363]=0
    // input layout: [n][1][s][a], a fastest
    for (int s = t; s < S; s += 384)
        xs[s] = x[(n * S + s) * A + a];
    __syncthreads();

    if (t < S) {
        const float* c = xs + t;
        const int rmax = 362 - t;
        float acL = 0.0f;
        float acR = 0.5f * c[0];
        #pragma unroll
        for (int j = 0; j < 181; ++j) {
            const int d = 2 * j + 1;
            const float h = -2.0f / ((float)(M_PI * M_PI) * (float)d * (float)d);
            if (d <= t)    acL = fmaf(c[-d], h, acL);
            if (d <= rmax) acR = fmaf(c[d],  h, acR);
        }
        ps[t + 1] = acL + acR;
    }
    __syncthreads();

    // write this batch's (mid, delta) half of the packed pair table
    float2* gr = ((float2*)&g_tab2[n >> 1][(size_t)a * RP]) + (n & 1);
    if (t < RP) {                        // k = t in [0, 363]
        const float p0 = ps[t];          // p[k-1]
        const float p1 = ps[t + 1];      // p[k]
        const float d  = p1 - p0;
        gr[2 * t] = make_float2(fmaf(0.5f, d, p0), d);
    }
}

#define CH 2                     // angles per pipeline chunk
#define NCHUNK (AH / CH)         // 45 (odd -> explicit pipeline tail below)
#define MAGICF 12582912.0f       // 2^23 + 2^22
#define MAGICI 0x4B400000

// grid (8, 32, 2): block = 32(x) x 8(y) spatial tile x angle-half; warp =
// 8(x) x 4(y) patch for gather locality. ALL 4 batches per thread: one index
// feeds two LDG.128. qp = xf*cos - yf*sin + 181.5; k = round(qp) via magic;
// value = mid + (qp-k)*delta.
__global__ __launch_bounds__(256) void backproject_kernel() {
    const int x0 = blockIdx.x * 32;
    const int y0 = blockIdx.y * 8;
    const int hf = blockIdx.z;
    const int abase = hf * AH;
    const int tid = threadIdx.x;
    const int w = tid >> 5, l = tid & 31;

    const int xx = x0 + ((w & 3) << 3) + (l & 7);
    const int yy = y0 + ((w >> 2) << 2) + (l >> 3);

    __shared__ float2 sc2[AH];   // (cos, sin) for angle abase+t

    if (tid < AH) {
        float sn, cs;
        sincosf((float)(abase + tid) * (float)(M_PI / 180.0), &sn, &cs);
        sc2[tid] = make_float2(cs, sn);
    }
    __syncthreads();

    const float xf = (float)(xx - 128);
    const float yf = (float)(yy - 128);
    const float4* __restrict__ tb0 = g_tab2[0] + (size_t)abase * RP;
    const float4* __restrict__ tb1 = g_tab2[1] + (size_t)abase * RP;

    float accm0 = 0.f, accm1 = 0.f, accm2 = 0.f, accm3 = 0.f;
    float accd0 = 0.f, accd1 = 0.f, accd2 = 0.f, accd3 = 0.f;

    float4 va0[CH], va1[CH], vb0[CH], vb1[CH];
    float  wa[CH], wb[CH];

    #define LOADC(c, v0, v1, ww)                                              \
        {                                                                     \
            const int a0 = (c) * CH;                                          \
            _Pragma("unroll")                                                 \
            for (int k = 0; k < CH; ++k) {                                    \
                const float2 cb = sc2[a0 + k];                                \
                const float qp = fmaf(xf, cb.x, fmaf(-yf, cb.y, 181.5f));     \
                const float f  = qp + MAGICF;                                 \
                const float il = f - MAGICF;             /* round(qp) */      \
                ww[k] = qp - il;                         /* in [-.5,.5] */    \
                const int i = (a0 + k) * RP + (__float_as_int(f) - MAGICI);   \
                v0[k] = __ldg(tb0 + i);                                       \
                v1[k] = __ldg(tb1 + i);                                       \
            }                                                                 \
        }

    #define ACCC(v0, v1, ww)                                                  \
        {                                                                     \
            _Pragma("unroll")                                                 \
            for (int k = 0; k < CH; ++k) {                                    \
                accm0 += v0[k].x;  accd0 = fmaf(ww[k], v0[k].y, accd0);       \
                accm1 += v0[k].z;  accd1 = fmaf(ww[k], v0[k].w, accd1);       \
                accm2 += v1[k].x;  accd2 = fmaf(ww[k], v1[k].y, accd2);       \
                accm3 += v1[k].z;  accd3 = fmaf(ww[k], v1[k].w, accd3);       \
            }                                                                 \
        }

    // Double-buffered pipeline over NCHUNK=45 chunks (odd), explicit tail.
    LOADC(0, va0, va1, wa)
    LOADC(1, vb0, vb1, wb)
    int c = 0;
    #pragma unroll 1
    for (; c + 3 < NCHUNK; c += 2) {
        ACCC(va0, va1, wa)
        LOADC(c + 2, va0, va1, wa)
        ACCC(vb0, vb1, wb)
        LOADC(c + 3, vb0, vb1, wb)
    }
    // here: va holds chunk c (=NCHUNK-3), vb holds c+1; chunk c+2 = NCHUNK-1 remains
    ACCC(va0, va1, wa)
    LOADC(c + 2, va0, va1, wa)
    ACCC(vb0, vb1, wb)
    ACCC(va0, va1, wa)

    #undef LOADC
    #undef ACCC

    float* o = g_part[hf] + (size_t)yy * W + xx;
    o[0 * W * W] = accm0 + accd0;
    o[1 * W * W] = accm1 + accd1;
    o[2 * W * W] = accm2 + accd2;
    o[3 * W * W] = accm3 + accd3;
}

// out = (part0 + part1) * pi/360, fully coalesced float4.
__global__ __launch_bounds__(256) void combine_kernel(float* __restrict__ out) {
    const int i = blockIdx.x * 256 + threadIdx.x;     // float4 index
    const float4 p0 = ((const float4*)g_part[0])[i];
    const float4 p1 = ((const float4*)g_part[1])[i];
    const float sc = (float)(M_PI / 360.0);
    float4 r;
    r.x = (p0.x + p1.x) * sc;
    r.y = (p0.y + p1.y) * sc;
    r.z = (p0.z + p1.z) * sc;
    r.w = (p0.w + p1.w) * sc;
    ((float4*)out)[i] = r;
}

extern "C" void kernel_launch(void* const* d_in, const int* in_sizes, int n_in,
                              void* d_out, int out_size) {
    const float* x = (const float*)d_in[0];
    float* out = (float*)d_out;

    ramp_filter_kernel<<<NB * A, 384>>>(x);
    backproject_kernel<<<dim3(8, 32, 2), 256>>>();
    combine_kernel<<<(NB * W * W / 4) / 256, 256>>>(out);
}